// round 5
// baseline (speedup 1.0000x reference)
#include <cuda_runtime.h>
#include <cstdint>

#define BB 32
#define HH 56
#define HC 128
#define CC 256
#define PIX (HH*HH)          // 3136
#define EZ (BB*HC*PIX)       // 12845056
#define N1 (BB*PIX)          // 100352
#define OHH 112
#define OPIX (OHH*OHH)       // 12544
#define N2 (BB*OPIX)         // 401408
#define KW1 (257*9)          // 2313

#define NCONVB (32*7*4)      // 896 conv1 blocks
#define NDECSL (32*13)       // 416 dec (batch, n-tile) slots

__device__ __align__(128) float g_z[EZ];        // conv1 out -> (in place) BEC output h
__device__ __align__(128) float g_wp[KW1*128];  // repacked w1: [ic*9+kk][oc]
__device__ float g_p1[NCONVB*128*2];            // conv1 per-block (sum, sumsq) partials
__device__ float g_p2[NDECSL*256*2];            // dec per-slot per-channel partials
__device__ float g_m1[HC], g_rs1[HC];
__device__ float g_m2[CC], g_rs2[CC];

// ---------------------------------------------------------------------------
// Kernel 0: repack w1 [oc][ic][kk] -> g_wp [ic*9+kk][oc]
// ---------------------------------------------------------------------------
__global__ __launch_bounds__(256) void repack_kernel(const float* __restrict__ w1) {
  int i = blockIdx.x * 256 + threadIdx.x;
  if (i < KW1 * 128) {
    int oc = i & 127, ickk = i >> 7;
    g_wp[ickk * 128 + oc] = w1[oc * KW1 + ickk];
  }
}

// ---------------------------------------------------------------------------
// Kernel 1: conv 3x3 s1 p1 + fused BN1 partial stats.
// ---------------------------------------------------------------------------
__global__ __launch_bounds__(256) void conv1_kernel(
    const float* __restrict__ x, const float* __restrict__ nu,
    const float* __restrict__ b1) {
  __shared__ float sIn[180];
  __shared__ float4 sW[288];
  const int t = threadIdx.x;
  const int bx = blockIdx.x, by = blockIdx.y, b = blockIdx.z;
  const float nf = nu[0] * 0.5f;

  const int og = t >> 4;
  const int p  = t & 15;
  const int row = p >> 1;
  const int cbase = (p & 1) * 8;
  const int r0 = by * 8, c0 = bx * 16;

  const int lr = t / 18, lc = t % 18;
  const int gy = r0 - 1 + lr, gx = c0 - 1 + lc;
  const bool inb = (t < 180) && (gy >= 0) && (gy < HH) && (gx >= 0) && (gx < HH);
  const long xoff = ((long)b * 256) * PIX + (long)gy * HH + gx;

  float acc[64];
#pragma unroll
  for (int i = 0; i < 64; ++i) acc[i] = 0.f;

  const float4* wp4 = (const float4*)g_wp;

  {
    float v = 0.f;
    if (inb) v = x[xoff];
    float4 wa = wp4[t];
    float4 wb;
    if (t < 32) wb = wp4[256 + t];
    if (t < 180) sIn[t] = v;
    sW[t] = wa;
    if (t < 32) sW[256 + t] = wb;
  }
  __syncthreads();

  float pin = 0.f;
  float4 pwa, pwb;

  for (int ic = 0; ic < 257; ++ic) {
    if (ic < 256) {
      const int icn = ic + 1;
      pin = 0.f;
      if (inb) pin = (icn < 256) ? x[xoff + (long)icn * PIX] : nf;
      pwa = wp4[icn * 288 + t];
      if (t < 32) pwb = wp4[icn * 288 + 256 + t];
    }
#pragma unroll
    for (int kh = 0; kh < 3; ++kh) {
      float inr[10];
#pragma unroll
      for (int j = 0; j < 10; ++j) inr[j] = sIn[(row + kh) * 18 + cbase + j];
#pragma unroll
      for (int kw = 0; kw < 3; ++kw) {
        const int kk = kh * 3 + kw;
        const float4 wa = sW[kk * 32 + og * 2];
        const float4 wb = sW[kk * 32 + og * 2 + 1];
#pragma unroll
        for (int j = 0; j < 8; ++j) {
          const float iv = inr[kw + j];
          acc[0 * 8 + j] += wa.x * iv;
          acc[1 * 8 + j] += wa.y * iv;
          acc[2 * 8 + j] += wa.z * iv;
          acc[3 * 8 + j] += wa.w * iv;
          acc[4 * 8 + j] += wb.x * iv;
          acc[5 * 8 + j] += wb.y * iv;
          acc[6 * 8 + j] += wb.z * iv;
          acc[7 * 8 + j] += wb.w * iv;
        }
      }
    }
    __syncthreads();
    if (ic < 256) {
      if (t < 180) sIn[t] = pin;
      sW[t] = pwa;
      if (t < 32) sW[256 + t] = pwb;
    }
    __syncthreads();
  }

  const bool valid = (c0 + cbase < HH);
  if (valid) {
#pragma unroll
    for (int ocl = 0; ocl < 8; ++ocl) {
      const int oc = og * 8 + ocl;
      const float bb = b1[oc];
      float* dst = g_z + ((b * 128 + oc) * HH + r0 + row) * HH + c0 + cbase;
      float4 v0 = {acc[ocl*8+0]+bb, acc[ocl*8+1]+bb, acc[ocl*8+2]+bb, acc[ocl*8+3]+bb};
      float4 v1 = {acc[ocl*8+4]+bb, acc[ocl*8+5]+bb, acc[ocl*8+6]+bb, acc[ocl*8+7]+bb};
      ((float4*)dst)[0] = v0;
      ((float4*)dst)[1] = v1;
    }
  }

  // fused BN1 partial stats: reduce over the 16 threads that share og
  const int bid = (b * 7 + by) * 4 + bx;
#pragma unroll
  for (int ocl = 0; ocl < 8; ++ocl) {
    const float bb = b1[og * 8 + ocl];
    float s = 0.f, q = 0.f;
    if (valid) {
#pragma unroll
      for (int j = 0; j < 8; ++j) {
        float v = acc[ocl * 8 + j] + bb;
        s += v; q += v * v;
      }
    }
#pragma unroll
    for (int m = 8; m >= 1; m >>= 1) {
      s += __shfl_xor_sync(0xffffffffu, s, m);
      q += __shfl_xor_sync(0xffffffffu, q, m);
    }
    if ((t & 15) == 0) {
      g_p1[(bid * 128 + og * 8 + ocl) * 2 + 0] = s;
      g_p1[(bid * 128 + og * 8 + ocl) * 2 + 1] = q;
    }
  }
}

// ---------------------------------------------------------------------------
// Kernel 2: reduce conv1 partials -> BN1 mean/rsqrt (double accumulate)
// ---------------------------------------------------------------------------
__global__ __launch_bounds__(256) void reduce1_kernel() {
  const int c = blockIdx.x, t = threadIdx.x;
  double s = 0.0, q = 0.0;
  for (int i = t; i < NCONVB; i += 256) {
    s += g_p1[(i * 128 + c) * 2 + 0];
    q += g_p1[(i * 128 + c) * 2 + 1];
  }
  __shared__ double ss[256], sq[256];
  ss[t] = s; sq[t] = q;
  __syncthreads();
  for (int o = 128; o > 0; o >>= 1) {
    if (t < o) { ss[t] += ss[t + o]; sq[t] += sq[t + o]; }
    __syncthreads();
  }
  if (t == 0) {
    double m   = ss[0] / N1;
    double var = sq[0] / N1 - m * m;
    g_m1[c]  = (float)m;
    g_rs1[c] = rsqrtf((float)var + 1e-5f);
  }
}

// ---------------------------------------------------------------------------
// Threefry2x32, key (0,42), partitionable draw: x0=0, x1=j, out = o0^o1.
// ---------------------------------------------------------------------------
__device__ __forceinline__ unsigned tf_xor(unsigned j) {
  const unsigned ks0 = 0u, ks1 = 42u, ks2 = 0x1BD11BDAu ^ 42u;
  unsigned x0 = 0u + ks0;
  unsigned x1 = j  + ks1;
#define TFRND(r) { x0 += x1; x1 = __funnelshift_l(x1, x1, r); x1 ^= x0; }
  TFRND(13) TFRND(15) TFRND(26) TFRND(6)
  x0 += ks1; x1 += ks2 + 1u;
  TFRND(17) TFRND(29) TFRND(16) TFRND(24)
  x0 += ks2; x1 += ks0 + 2u;
  TFRND(13) TFRND(15) TFRND(26) TFRND(6)
  x0 += ks0; x1 += ks1 + 3u;
  TFRND(17) TFRND(29) TFRND(16) TFRND(24)
  x0 += ks1; x1 += ks2 + 4u;
  TFRND(13) TFRND(15) TFRND(26) TFRND(6)
  x0 += ks2; x1 += ks0 + 5u;
#undef TFRND
  return x0 ^ x1;
}

// ---------------------------------------------------------------------------
// Kernel 3: BN1 apply + sigmoid + quantize + BEC (in place on g_z)
// ---------------------------------------------------------------------------
__global__ __launch_bounds__(256) void bec_kernel(
    const float* __restrict__ nu, const float* __restrict__ g1,
    const float* __restrict__ be1) {
  const int e = blockIdx.x * 256 + threadIdx.x;
  const int c = (e / PIX) & 127;
  const float z = g_z[e];
  float tt = (z - g_m1[c]) * g_rs1[c] * g1[c] + be1[c];
  float s  = 0.5f * tanhf(0.5f * tt) + 0.5f;
  float r  = rintf(s * 256.0f);
  if (r >= 256.0f) r -= 256.0f;
  const unsigned xb = (unsigned)r;

  const float q = 1.0f - nu[0] * 0.5f;
  unsigned mask = 0u;
#pragma unroll
  for (int k = 0; k < 8; ++k) {
    unsigned bits = tf_xor((unsigned)(k * EZ + e));
    float u = __uint_as_float((bits >> 9) | 0x3f800000u) - 1.0f;
    if (u < q) mask |= (1u << k);
  }
  float outv = ((float)(xb & mask) + (255.0f - (float)mask) / 2.0f) / 255.0f;
  g_z[e] = outv;
}

// ---------------------------------------------------------------------------
// Kernel 4: decoder GEMM on mma.sync tf32, A hi/lo split in registers.
// Block: 128m x 256n, K=128 resident.  512 threads = 2m x 8n warps,
// warp tile 64m x 32n.  Fused BN2 partial stats in epilogue.
// smem: sA raw fp32 [128m][132] + sB [128k][264] = 198 KB.
// ---------------------------------------------------------------------------
#define DA_STR 132
#define DB_STR 264
#define SM_B_OFF (128*DA_STR)
#define SM_DEC_B ((128*DA_STR + 128*DB_STR)*4)

__global__ __launch_bounds__(512) void dec_mma_kernel(
    const float* __restrict__ w4, const float* __restrict__ b4,
    float* __restrict__ out) {
  extern __shared__ float sm[];
  float* sA = sm;
  float* sB = sm + SM_B_OFF;

  const int t = threadIdx.x;
  const int lane = t & 31, wid = t >> 5;
  const int wm = wid >> 3, wn = wid & 7;     // 2 x 8 warp grid
  const int g = lane >> 2, tig = lane & 3;
  const int nblk = blockIdx.x;
  const int nb   = nblk * 256;
  const int mblk = blockIdx.y;
  const int b    = blockIdx.z;

  // stage A raw fp32 [m][k]  (w4 is [k][m_global])
  for (int i = t; i < 128 * 128; i += 512) {
    int m = i & 127, k = i >> 7;
    sA[m * DA_STR + k] = w4[k * 1024 + mblk * 128 + m];
  }
  // stage B [k][n] = h[k][nb+n], zero-pad past PIX
  for (int i = t; i < 128 * 256; i += 512) {
    int n = i & 255, k = i >> 8;
    int pix = nb + n;
    sB[k * DB_STR + n] = (pix < PIX) ? g_z[(b * 128 + k) * PIX + pix] : 0.f;
  }
  __syncthreads();

  float acc[4][4][4];
#pragma unroll
  for (int mt = 0; mt < 4; ++mt)
#pragma unroll
    for (int nt = 0; nt < 4; ++nt)
#pragma unroll
      for (int j = 0; j < 4; ++j) acc[mt][nt][j] = 0.f;

#define MMA(d, a, b0, b1)                                                     \
  asm volatile(                                                               \
      "mma.sync.aligned.m16n8k8.row.col.f32.tf32.tf32.f32 "                   \
      "{%0,%1,%2,%3}, {%4,%5,%6,%7}, {%8,%9}, {%0,%1,%2,%3};"                 \
      : "+f"((d)[0]), "+f"((d)[1]), "+f"((d)[2]), "+f"((d)[3])                \
      : "r"((a)[0]), "r"((a)[1]), "r"((a)[2]), "r"((a)[3]), "r"(b0), "r"(b1))

  for (int ks = 0; ks < 16; ++ks) {
    const int kb = ks * 8;
    uint32_t bf[4][2];
#pragma unroll
    for (int nt = 0; nt < 4; ++nt) {
      const float* p = sB + (kb + tig) * DB_STR + wn * 32 + nt * 8 + g;
      bf[nt][0] = __float_as_uint(p[0]);
      bf[nt][1] = __float_as_uint(p[4 * DB_STR]);
    }
    float ar[4][4];
    uint32_t ah[4][4];
#pragma unroll
    for (int mt = 0; mt < 4; ++mt) {
      const float* p = sA + (wm * 64 + mt * 16 + g) * DA_STR + kb + tig;
      ar[mt][0] = p[0];
      ar[mt][1] = p[8 * DA_STR];
      ar[mt][2] = p[4];
      ar[mt][3] = p[8 * DA_STR + 4];
#pragma unroll
      for (int i = 0; i < 4; ++i)
        asm("cvt.rna.tf32.f32 %0, %1;" : "=r"(ah[mt][i]) : "f"(ar[mt][i]));
    }
#pragma unroll
    for (int mt = 0; mt < 4; ++mt)
#pragma unroll
      for (int nt = 0; nt < 4; ++nt) MMA(acc[mt][nt], ah[mt], bf[nt][0], bf[nt][1]);
    // lo pass: reuse ah registers
#pragma unroll
    for (int mt = 0; mt < 4; ++mt)
#pragma unroll
      for (int i = 0; i < 4; ++i) {
        float lo = ar[mt][i] - __uint_as_float(ah[mt][i]);
        asm("cvt.rna.tf32.f32 %0, %1;" : "=r"(ah[mt][i]) : "f"(lo));
      }
#pragma unroll
    for (int mt = 0; mt < 4; ++mt)
#pragma unroll
      for (int nt = 0; nt < 4; ++nt) MMA(acc[mt][nt], ah[mt], bf[nt][0], bf[nt][1]);
  }
#undef MMA

  __syncthreads();   // compute done; safe to overlay stats into sA region
  float* sS = sm;           // [128 m_local][32 (wn*4+tig)]
  float* sQ = sm + 4096;
  float* sM = sm + 8192;    // [128][2]

  // epilogue: store (+bias) with 2x2 scatter, accumulate per-row stats
#pragma unroll
  for (int mt = 0; mt < 4; ++mt) {
#pragma unroll
    for (int half = 0; half < 2; ++half) {
      const int m_local = wm * 64 + mt * 16 + g + half * 8;
      const int m = mblk * 128 + m_local;
      const int c = m >> 2, th = (m >> 1) & 1, tw = m & 1;
      const float bb = b4[c];
      float* orow = out + ((b * 256 + c) * OHH + th) * OHH + tw;
      float s = 0.f, q = 0.f;
#pragma unroll
      for (int nt = 0; nt < 4; ++nt) {
        const int n0 = nb + wn * 32 + nt * 8 + tig * 2;
#pragma unroll
        for (int jj = 0; jj < 2; ++jj) {
          const int pix = n0 + jj;
          if (pix < PIX) {
            const int ih = pix / HH, iw = pix - ih * HH;
            const float v = acc[mt][nt][half * 2 + jj] + bb;
            orow[(2 * ih) * OHH + 2 * iw] = v;
            s += v; q += v * v;
          }
        }
      }
      sS[m_local * 32 + wn * 4 + tig] = s;
      sQ[m_local * 32 + wn * 4 + tig] = q;
    }
  }
  __syncthreads();
  if (t < 128) {
    float s = 0.f, q = 0.f;
#pragma unroll
    for (int i = 0; i < 32; ++i) { s += sS[t * 32 + i]; q += sQ[t * 32 + i]; }
    sM[t * 2 + 0] = s;
    sM[t * 2 + 1] = q;
  }
  __syncthreads();
  if (t < 32) {
    float s = sM[(t*4+0)*2] + sM[(t*4+1)*2] + sM[(t*4+2)*2] + sM[(t*4+3)*2];
    float q = sM[(t*4+0)*2+1] + sM[(t*4+1)*2+1] + sM[(t*4+2)*2+1] + sM[(t*4+3)*2+1];
    const int slot = b * 13 + nblk;
    g_p2[(slot * 256 + mblk * 32 + t) * 2 + 0] = s;
    g_p2[(slot * 256 + mblk * 32 + t) * 2 + 1] = q;
  }
}

// ---------------------------------------------------------------------------
// Kernel 5: reduce dec partials -> BN2 mean/rsqrt
// ---------------------------------------------------------------------------
__global__ __launch_bounds__(128) void reduce2_kernel() {
  const int c = blockIdx.x, t = threadIdx.x;
  double s = 0.0, q = 0.0;
  for (int i = t; i < NDECSL; i += 128) {
    s += g_p2[(i * 256 + c) * 2 + 0];
    q += g_p2[(i * 256 + c) * 2 + 1];
  }
  __shared__ double ss[128], sq[128];
  ss[t] = s; sq[t] = q;
  __syncthreads();
  for (int o = 64; o > 0; o >>= 1) {
    if (t < o) { ss[t] += ss[t + o]; sq[t] += sq[t + o]; }
    __syncthreads();
  }
  if (t == 0) {
    double m   = ss[0] / N2;
    double var = sq[0] / N2 - m * m;
    g_m2[c]  = (float)m;
    g_rs2[c] = rsqrtf((float)var + 1e-5f);
  }
}

// ---------------------------------------------------------------------------
// Kernel 6: BN2 apply + relu, in place on d_out
// ---------------------------------------------------------------------------
__global__ __launch_bounds__(256) void bn2_kernel(
    const float* __restrict__ g2, const float* __restrict__ be2,
    float* __restrict__ out) {
  const int i = blockIdx.x * 256 + threadIdx.x;
  const int c = (i / (OPIX / 4)) & 255;
  float4 v = ((float4*)out)[i];
  const float m = g_m2[c], rs = g_rs2[c], gg = g2[c], bb = be2[c];
  v.x = fmaxf((v.x - m) * rs * gg + bb, 0.f);
  v.y = fmaxf((v.y - m) * rs * gg + bb, 0.f);
  v.z = fmaxf((v.z - m) * rs * gg + bb, 0.f);
  v.w = fmaxf((v.w - m) * rs * gg + bb, 0.f);
  ((float4*)out)[i] = v;
}

// ---------------------------------------------------------------------------
extern "C" void kernel_launch(void* const* d_in, const int* in_sizes, int n_in,
                              void* d_out, int out_size) {
  const float* x   = (const float*)d_in[0];
  const float* nu  = (const float*)d_in[1];
  const float* w1  = (const float*)d_in[2];
  const float* b1  = (const float*)d_in[3];
  const float* g1  = (const float*)d_in[4];
  const float* be1 = (const float*)d_in[5];
  const float* w4  = (const float*)d_in[6];
  const float* b4  = (const float*)d_in[7];
  const float* g2  = (const float*)d_in[8];
  const float* be2 = (const float*)d_in[9];
  float* out = (float*)d_out;

  cudaFuncSetAttribute(dec_mma_kernel, cudaFuncAttributeMaxDynamicSharedMemorySize, SM_DEC_B);

  repack_kernel<<<(KW1 * 128 + 255) / 256, 256>>>(w1);
  conv1_kernel<<<dim3(4, 7, 32), 256>>>(x, nu, b1);
  reduce1_kernel<<<128, 256>>>();
  bec_kernel<<<EZ / 256, 256>>>(nu, g1, be1);
  dec_mma_kernel<<<dim3(13, 8, 32), 512, SM_DEC_B>>>(w4, b4, out);
  reduce2_kernel<<<256, 128>>>();
  bn2_kernel<<<out_size / 4 / 256, 256>>>(g2, be2, out);
}

// round 6
// speedup vs baseline: 1.1722x; 1.1722x over previous
#include <cuda_runtime.h>
#include <cstdint>

#define BB 32
#define HH 56
#define HC 128
#define CC 256
#define PIX (HH*HH)          // 3136
#define EZ (BB*HC*PIX)       // 12845056
#define N1 (BB*PIX)          // 100352
#define OHH 112
#define OPIX (OHH*OHH)       // 12544
#define N2 (BB*OPIX)         // 401408
#define KW1 (257*9)          // 2313

__device__ __align__(128) float g_z[EZ];        // conv1 out -> (in place) BEC output h
__device__ __align__(128) float g_wp[KW1*128];  // repacked w1: [ic*9+kk][oc]
__device__ double g_d1[128*8*2];                // BN1 partials (sum, sumsq)
__device__ double g_d2[256*8*2];                // BN2 partials
__device__ float g_m1[HC], g_rs1[HC];
__device__ float g_m2[CC], g_rs2[CC];

// ---------------------------------------------------------------------------
// Kernel 0: repack w1 [oc][ic][kk] -> g_wp [ic*9+kk][oc]
// ---------------------------------------------------------------------------
__global__ __launch_bounds__(256) void repack_kernel(const float* __restrict__ w1) {
  int i = blockIdx.x * 256 + threadIdx.x;
  if (i < KW1 * 128) {
    int oc = i & 127, ickk = i >> 7;
    g_wp[ickk * 128 + oc] = w1[oc * KW1 + ickk];
  }
}

// ---------------------------------------------------------------------------
// Kernel 1: conv 3x3 s1 p1, 257 in-ch (ch256 = noise const), 128 out-ch.
// Tile: 128 oc x (8 x 16) px, 256 threads, 8oc x 8px microtile.
// Double-buffered smem: ONE __syncthreads per ic iteration.
// ---------------------------------------------------------------------------
__global__ __launch_bounds__(256) void conv1_kernel(
    const float* __restrict__ x, const float* __restrict__ nu,
    const float* __restrict__ b1) {
  __shared__ float sIn[2][180];
  __shared__ float4 sW[2][288];
  const int t = threadIdx.x;
  const int bx = blockIdx.x, by = blockIdx.y, b = blockIdx.z;
  const float nf = nu[0] * 0.5f;

  const int og = t >> 4;
  const int p  = t & 15;
  const int row = p >> 1;
  const int cbase = (p & 1) * 8;
  const int r0 = by * 8, c0 = bx * 16;

  const int lr = t / 18, lc = t % 18;
  const int gy = r0 - 1 + lr, gx = c0 - 1 + lc;
  const bool inb = (t < 180) && (gy >= 0) && (gy < HH) && (gx >= 0) && (gx < HH);
  const long xoff = ((long)b * 256) * PIX + (long)gy * HH + gx;

  float acc[64];
#pragma unroll
  for (int i = 0; i < 64; ++i) acc[i] = 0.f;

  const float4* wp4 = (const float4*)g_wp;

  // prologue: stage ic=0 into buffer 0
  {
    float v = 0.f;
    if (inb) v = x[xoff];
    float4 wa = wp4[t];
    float4 wb;
    if (t < 32) wb = wp4[256 + t];
    if (t < 180) sIn[0][t] = v;
    sW[0][t] = wa;
    if (t < 32) sW[0][256 + t] = wb;
  }
  __syncthreads();

  float pin = 0.f;
  float4 pwa, pwb;

  for (int ic = 0; ic < 257; ++ic) {
    const int cur = ic & 1, nxt = cur ^ 1;
    // prefetch ic+1 into registers (overlaps compute)
    if (ic < 256) {
      const int icn = ic + 1;
      pin = 0.f;
      if (inb) pin = (icn < 256) ? x[xoff + (long)icn * PIX] : nf;
      pwa = wp4[icn * 288 + t];
      if (t < 32) pwb = wp4[icn * 288 + 256 + t];
    }
    // compute current ic from buffer cur
#pragma unroll
    for (int kh = 0; kh < 3; ++kh) {
      float inr[10];
#pragma unroll
      for (int j = 0; j < 10; ++j) inr[j] = sIn[cur][(row + kh) * 18 + cbase + j];
#pragma unroll
      for (int kw = 0; kw < 3; ++kw) {
        const int kk = kh * 3 + kw;
        const float4 wa = sW[cur][kk * 32 + og * 2];
        const float4 wb = sW[cur][kk * 32 + og * 2 + 1];
#pragma unroll
        for (int j = 0; j < 8; ++j) {
          const float iv = inr[kw + j];
          acc[0 * 8 + j] += wa.x * iv;
          acc[1 * 8 + j] += wa.y * iv;
          acc[2 * 8 + j] += wa.z * iv;
          acc[3 * 8 + j] += wa.w * iv;
          acc[4 * 8 + j] += wb.x * iv;
          acc[5 * 8 + j] += wb.y * iv;
          acc[6 * 8 + j] += wb.z * iv;
          acc[7 * 8 + j] += wb.w * iv;
        }
      }
    }
    // store prefetched ic+1 into buffer nxt (nobody reads nxt this iteration)
    if (ic < 256) {
      if (t < 180) sIn[nxt][t] = pin;
      sW[nxt][t] = pwa;
      if (t < 32) sW[nxt][256 + t] = pwb;
    }
    __syncthreads();
  }

  if (c0 + cbase < HH) {
#pragma unroll
    for (int ocl = 0; ocl < 8; ++ocl) {
      const int oc = og * 8 + ocl;
      const float bb = b1[oc];
      float* dst = g_z + ((b * 128 + oc) * HH + r0 + row) * HH + c0 + cbase;
      float4 v0 = {acc[ocl*8+0]+bb, acc[ocl*8+1]+bb, acc[ocl*8+2]+bb, acc[ocl*8+3]+bb};
      float4 v1 = {acc[ocl*8+4]+bb, acc[ocl*8+5]+bb, acc[ocl*8+6]+bb, acc[ocl*8+7]+bb};
      ((float4*)dst)[0] = v0;
      ((float4*)dst)[1] = v1;
    }
  }
}

// ---------------------------------------------------------------------------
// Kernel 2a: BN1 partial stats — grid (128 ch, 8 slices), 4 batches/slice
// ---------------------------------------------------------------------------
__global__ __launch_bounds__(256) void stats1a_kernel() {
  const int c = blockIdx.x, sl = blockIdx.y, t = threadIdx.x;
  double s = 0.0, q = 0.0;
  for (int bb = sl * 4; bb < sl * 4 + 4; ++bb) {
    const float4* p = (const float4*)(g_z + (bb * 128 + c) * PIX);
    for (int i = t; i < PIX / 4; i += 256) {
      float4 v = p[i];
      s += (double)v.x + v.y + v.z + v.w;
      q += (double)v.x * v.x + (double)v.y * v.y +
           (double)v.z * v.z + (double)v.w * v.w;
    }
  }
  __shared__ double ss[256], sq[256];
  ss[t] = s; sq[t] = q;
  __syncthreads();
  for (int o = 128; o > 0; o >>= 1) {
    if (t < o) { ss[t] += ss[t + o]; sq[t] += sq[t + o]; }
    __syncthreads();
  }
  if (t == 0) {
    g_d1[(c * 8 + sl) * 2 + 0] = ss[0];
    g_d1[(c * 8 + sl) * 2 + 1] = sq[0];
  }
}

// Kernel 2b: final BN1 reduce (one block, 128 threads = channels)
__global__ __launch_bounds__(128) void reduce1_kernel() {
  const int c = threadIdx.x;
  double s = 0.0, q = 0.0;
#pragma unroll
  for (int sl = 0; sl < 8; ++sl) {
    s += g_d1[(c * 8 + sl) * 2 + 0];
    q += g_d1[(c * 8 + sl) * 2 + 1];
  }
  double m   = s / N1;
  double var = q / N1 - m * m;
  g_m1[c]  = (float)m;
  g_rs1[c] = rsqrtf((float)var + 1e-5f);
}

// ---------------------------------------------------------------------------
// Threefry2x32, key (0,42), partitionable draw: x0=0, x1=j, out = o0^o1.
// ---------------------------------------------------------------------------
__device__ __forceinline__ unsigned tf_xor(unsigned j) {
  const unsigned ks0 = 0u, ks1 = 42u, ks2 = 0x1BD11BDAu ^ 42u;
  unsigned x0 = 0u + ks0;
  unsigned x1 = j  + ks1;
#define TFRND(r) { x0 += x1; x1 = __funnelshift_l(x1, x1, r); x1 ^= x0; }
  TFRND(13) TFRND(15) TFRND(26) TFRND(6)
  x0 += ks1; x1 += ks2 + 1u;
  TFRND(17) TFRND(29) TFRND(16) TFRND(24)
  x0 += ks2; x1 += ks0 + 2u;
  TFRND(13) TFRND(15) TFRND(26) TFRND(6)
  x0 += ks0; x1 += ks1 + 3u;
  TFRND(17) TFRND(29) TFRND(16) TFRND(24)
  x0 += ks1; x1 += ks2 + 4u;
  TFRND(13) TFRND(15) TFRND(26) TFRND(6)
  x0 += ks2; x1 += ks0 + 5u;
#undef TFRND
  return x0 ^ x1;
}

// ---------------------------------------------------------------------------
// Kernel 3: BN1 apply + sigmoid + quantize + BEC (in place on g_z)
// ---------------------------------------------------------------------------
__global__ __launch_bounds__(256) void bec_kernel(
    const float* __restrict__ nu, const float* __restrict__ g1,
    const float* __restrict__ be1) {
  const int e = blockIdx.x * 256 + threadIdx.x;
  const int c = (e / PIX) & 127;
  const float z = g_z[e];
  float tt = (z - g_m1[c]) * g_rs1[c] * g1[c] + be1[c];
  float s  = 0.5f * tanhf(0.5f * tt) + 0.5f;
  float r  = rintf(s * 256.0f);
  if (r >= 256.0f) r -= 256.0f;
  const unsigned xb = (unsigned)r;

  const float q = 1.0f - nu[0] * 0.5f;
  unsigned mask = 0u;
#pragma unroll
  for (int k = 0; k < 8; ++k) {
    unsigned bits = tf_xor((unsigned)(k * EZ + e));
    float u = __uint_as_float((bits >> 9) | 0x3f800000u) - 1.0f;
    if (u < q) mask |= (1u << k);
  }
  float outv = ((float)(xb & mask) + (255.0f - (float)mask) / 2.0f) / 255.0f;
  g_z[e] = outv;
}

// ---------------------------------------------------------------------------
// Kernel 4: ConvTranspose2d(k2,s2) as 4-tap GEMM (round-2 FFMA version).
// Tile: 64 px x 64 oc x 4 taps; 256 threads, 8px x 2c x 4tap = 64 acc each.
// ---------------------------------------------------------------------------
__global__ __launch_bounds__(256) void dec_kernel(
    const float* __restrict__ w4, const float* __restrict__ b4,
    float* __restrict__ out) {
  __shared__ float4 ws4[16 * 64];   // [hc-chunk][c-local] -> 4 taps
  __shared__ float4 hs4[16 * 16];   // [hc-chunk][px/4]
  const int t = threadIdx.x;
  const int bp = blockIdx.x;
  const int b = bp / 49;
  const int pixb = (bp % 49) * 64;
  const int cb = blockIdx.y * 64;
  const int pgrp = t & 7;
  const int cgrp = t >> 3;

  float acc[64];
#pragma unroll
  for (int i = 0; i < 64; ++i) acc[i] = 0.f;

  const float4* w44 = (const float4*)w4;
  const float4* gz4 = (const float4*)g_z;

  for (int hc0 = 0; hc0 < 128; hc0 += 16) {
    __syncthreads();
#pragma unroll
    for (int i = 0; i < 4; ++i) {
      int idx = t + i * 256;
      int hh = idx >> 6, cl = idx & 63;
      ws4[idx] = w44[(hc0 + hh) * 256 + cb + cl];
    }
    {
      int hh = t >> 4, p4 = t & 15;
      hs4[t] = gz4[((b * 128 + hc0 + hh) * PIX + pixb) / 4 + p4];
    }
    __syncthreads();
#pragma unroll
    for (int hh = 0; hh < 16; ++hh) {
      const float4 h0 = hs4[hh * 16 + pgrp * 2];
      const float4 h1 = hs4[hh * 16 + pgrp * 2 + 1];
      const float4 wa = ws4[hh * 64 + cgrp * 2];
      const float4 wb = ws4[hh * 64 + cgrp * 2 + 1];
      const float hv[8] = {h0.x, h0.y, h0.z, h0.w, h1.x, h1.y, h1.z, h1.w};
#pragma unroll
      for (int pp = 0; pp < 8; ++pp) {
        acc[pp * 4 + 0] += hv[pp] * wa.x;
        acc[pp * 4 + 1] += hv[pp] * wa.y;
        acc[pp * 4 + 2] += hv[pp] * wa.z;
        acc[pp * 4 + 3] += hv[pp] * wa.w;
        acc[32 + pp * 4 + 0] += hv[pp] * wb.x;
        acc[32 + pp * 4 + 1] += hv[pp] * wb.y;
        acc[32 + pp * 4 + 2] += hv[pp] * wb.z;
        acc[32 + pp * 4 + 3] += hv[pp] * wb.w;
      }
    }
  }

#pragma unroll
  for (int cc = 0; cc < 2; ++cc) {
    const int c = cb + cgrp * 2 + cc;
    const float bb = b4[c];
#pragma unroll
    for (int pp = 0; pp < 8; ++pp) {
      const int pix = pixb + pgrp * 8 + pp;
      const int ih = pix / HH, iw = pix % HH;
      float* dst = out + ((b * 256 + c) * OHH + 2 * ih) * OHH + 2 * iw;
      float2 top = {acc[cc * 32 + pp * 4 + 0] + bb, acc[cc * 32 + pp * 4 + 1] + bb};
      float2 bot = {acc[cc * 32 + pp * 4 + 2] + bb, acc[cc * 32 + pp * 4 + 3] + bb};
      *(float2*)dst = top;
      *(float2*)(dst + OHH) = bot;
    }
  }
}

// ---------------------------------------------------------------------------
// Kernel 5a: BN2 partial stats — grid (256 ch, 8 slices), 4 batches/slice
// ---------------------------------------------------------------------------
__global__ __launch_bounds__(256) void stats2a_kernel(const float* __restrict__ out) {
  const int c = blockIdx.x, sl = blockIdx.y, t = threadIdx.x;
  double s = 0.0, q = 0.0;
  for (int bb = sl * 4; bb < sl * 4 + 4; ++bb) {
    const float4* p = (const float4*)(out + (bb * 256 + c) * OPIX);
    for (int i = t; i < OPIX / 4; i += 256) {
      float4 v = p[i];
      s += (double)v.x + v.y + v.z + v.w;
      q += (double)v.x * v.x + (double)v.y * v.y +
           (double)v.z * v.z + (double)v.w * v.w;
    }
  }
  __shared__ double ss[256], sq[256];
  ss[t] = s; sq[t] = q;
  __syncthreads();
  for (int o = 128; o > 0; o >>= 1) {
    if (t < o) { ss[t] += ss[t + o]; sq[t] += sq[t + o]; }
    __syncthreads();
  }
  if (t == 0) {
    g_d2[(c * 8 + sl) * 2 + 0] = ss[0];
    g_d2[(c * 8 + sl) * 2 + 1] = sq[0];
  }
}

// Kernel 5b: final BN2 reduce (one block, 256 threads = channels)
__global__ __launch_bounds__(256) void reduce2_kernel() {
  const int c = threadIdx.x;
  double s = 0.0, q = 0.0;
#pragma unroll
  for (int sl = 0; sl < 8; ++sl) {
    s += g_d2[(c * 8 + sl) * 2 + 0];
    q += g_d2[(c * 8 + sl) * 2 + 1];
  }
  double m   = s / N2;
  double var = q / N2 - m * m;
  g_m2[c]  = (float)m;
  g_rs2[c] = rsqrtf((float)var + 1e-5f);
}

// ---------------------------------------------------------------------------
// Kernel 6: BN2 apply + relu, in place on d_out
// ---------------------------------------------------------------------------
__global__ __launch_bounds__(256) void bn2_kernel(
    const float* __restrict__ g2, const float* __restrict__ be2,
    float* __restrict__ out) {
  const int i = blockIdx.x * 256 + threadIdx.x;
  const int c = (i / (OPIX / 4)) & 255;
  float4 v = ((float4*)out)[i];
  const float m = g_m2[c], rs = g_rs2[c], gg = g2[c], bb = be2[c];
  v.x = fmaxf((v.x - m) * rs * gg + bb, 0.f);
  v.y = fmaxf((v.y - m) * rs * gg + bb, 0.f);
  v.z = fmaxf((v.z - m) * rs * gg + bb, 0.f);
  v.w = fmaxf((v.w - m) * rs * gg + bb, 0.f);
  ((float4*)out)[i] = v;
}

// ---------------------------------------------------------------------------
extern "C" void kernel_launch(void* const* d_in, const int* in_sizes, int n_in,
                              void* d_out, int out_size) {
  const float* x   = (const float*)d_in[0];
  const float* nu  = (const float*)d_in[1];
  const float* w1  = (const float*)d_in[2];
  const float* b1  = (const float*)d_in[3];
  const float* g1  = (const float*)d_in[4];
  const float* be1 = (const float*)d_in[5];
  const float* w4  = (const float*)d_in[6];
  const float* b4  = (const float*)d_in[7];
  const float* g2  = (const float*)d_in[8];
  const float* be2 = (const float*)d_in[9];
  float* out = (float*)d_out;

  repack_kernel<<<(KW1 * 128 + 255) / 256, 256>>>(w1);
  conv1_kernel<<<dim3(4, 7, 32), 256>>>(x, nu, b1);
  stats1a_kernel<<<dim3(128, 8), 256>>>();
  reduce1_kernel<<<1, 128>>>();
  bec_kernel<<<EZ / 256, 256>>>(nu, g1, be1);
  dec_kernel<<<dim3(32 * 49, 4), 256>>>(w4, b4, out);
  stats2a_kernel<<<dim3(256, 8), 256>>>(out);
  reduce2_kernel<<<1, 256>>>();
  bn2_kernel<<<out_size / 4 / 256, 256>>>(g2, be2, out);
}